// round 15
// baseline (speedup 1.0000x reference)
#include <cuda_runtime.h>
#include <stdint.h>
#include <math.h>

constexpr int Bn   = 4;
constexpr int Tn   = 480000;
constexpr int DIMn = 9;
constexpr int CHUNK = 256;
constexpr int TPB   = 128;
constexpr int SPT   = CHUNK / TPB;               // 2
constexpr int NCH   = Tn / CHUNK;                // 1875 (exact)
constexpr int K1_CPB = 4;                        // chunks (warps) per K1 block
constexpr int K1_GX  = (NCH + K1_CPB - 1) / K1_CPB;  // 469

constexpr float LO_NORMAL = -0.99999994f;
constexpr float SQRT2F    = 1.41421356237309504880f;
constexpr float RCP48K    = 2.08333333333333333e-05f;  // fl(1/48000)
constexpr float EXP_M5    = 6.73794700e-03f;           // e^-5 (tail bound)

struct RandIniFx { uint32_t v[Bn * DIMn]; };
struct NKey      { uint32_t k0, k1; };

// per-(b) per-chunk EXACT fundamental phase sums; K2 -> exclusive prefixes
__device__ uint32_t g_pre0[Bn * NCH];

// ---------------- packed f32x2 helpers (sm_103a FFMA2/FMUL2) ----------------
#define PK2(o, lo, hi) \
  asm("mov.b64 %0, {%1, %2};" : "=l"(o) : "r"(__float_as_uint(lo)), "r"(__float_as_uint(hi)))
#define UPK2(lo, hi, in) do { unsigned _l, _h; \
  asm("mov.b64 {%0, %1}, %2;" : "=r"(_l), "=r"(_h) : "l"(in)); \
  (lo) = __uint_as_float(_l); (hi) = __uint_as_float(_h); } while (0)
#define MUL2(o, a, b) \
  asm("mul.rn.f32x2 %0, %1, %2;" : "=l"(o) : "l"(a), "l"(b))
#define ADD2(o, a, b) \
  asm("add.rn.f32x2 %0, %1, %2;" : "=l"(o) : "l"(a), "l"(b))
#define FMA2(o, a, b, c) \
  asm("fma.rn.f32x2 %0, %1, %2, %3;" : "=l"(o) : "l"(a), "l"(b), "l"(c))

// ---------------- threefry2x32-20 ----------------
__host__ __device__ __forceinline__ uint32_t rotl32(uint32_t x, int r) {
#ifdef __CUDA_ARCH__
  return __funnelshift_l(x, x, r);
#else
  return (x << r) | (x >> (32 - r));
#endif
}

__host__ __device__ __forceinline__ void tf2x32(uint32_t k0, uint32_t k1,
                                                uint32_t x0, uint32_t x1,
                                                uint32_t& o0, uint32_t& o1) {
  uint32_t k2 = k0 ^ k1 ^ 0x1BD11BDAu;
#define TFR(r) { x0 += x1; x1 = rotl32(x1, (r)); x1 ^= x0; }
  x0 += k0; x1 += k1;
  TFR(13) TFR(15) TFR(26) TFR(6)
  x0 += k1; x1 += k2 + 1u;
  TFR(17) TFR(29) TFR(16) TFR(24)
  x0 += k2; x1 += k0 + 2u;
  TFR(13) TFR(15) TFR(26) TFR(6)
  x0 += k0; x1 += k1 + 3u;
  TFR(17) TFR(29) TFR(16) TFR(24)
  x0 += k1; x1 += k2 + 4u;
  TFR(13) TFR(15) TFR(26) TFR(6)
  x0 += k2; x1 += k0 + 5u;
#undef TFR
  o0 = x0; o1 = x1;
}

__host__ __device__ __forceinline__ uint32_t rng_bits(uint32_t k0, uint32_t k1,
                                                      uint32_t idx) {
  uint32_t a, b;
  tf2x32(k0, k1, 0u, idx, a, b);
  return a ^ b;
}

__host__ __device__ __forceinline__ float bits01(uint32_t bits) {
  union { uint32_t u; float f; } c;
  c.u = (bits >> 9) | 0x3F800000u;
  return c.f - 1.0f;
}

// erfinv tail branch (w >= 5), from x and l2 = log2(1-x^2). Inline, rare.
__device__ __forceinline__ float erfinv_tail(float x, float l2) {
  float w = l2 * -0.693147181f;        // -ln(1-x^2)
  float s = sqrtf(w) - 3.0f;
  float p =            -0.000200214257f;
  p = fmaf(p, s,  0.000100950558f);
  p = fmaf(p, s,  0.00134934322f);
  p = fmaf(p, s, -0.00367342844f);
  p = fmaf(p, s,  0.00573950773f);
  p = fmaf(p, s, -0.0076224613f);
  p = fmaf(p, s,  0.00943887047f);
  p = fmaf(p, s,  1.00167406f);
  p = fmaf(p, s,  2.83297682f);
  return p * x;
}

// correctly-rounded x/48000 via Markstein (bit-identical to __fdiv_rn)
__device__ __forceinline__ float div48k(float x) {
  float q0 = __fmul_rn(x, RCP48K);
  float e  = fmaf(-48000.0f, q0, x);
  return fmaf(e, RCP48K, q0);
}

// fundamental rad in u32 fixed point, lsb = 2^-32 turns
__device__ __forceinline__ uint32_t rad0_fx32(float f0v) {
  float rad = div48k(f0v);
  return __float2uint_rn(rad * 4294967296.0f);
}

// ---------------- K1: warp-per-chunk fundamental sums ----------------------
__global__ void __launch_bounds__(TPB) k_chunksum0(const float* __restrict__ f0) {
  int b = blockIdx.y;
  int tid = threadIdx.x;
  int warp = tid >> 5, lane = tid & 31;
  int c = blockIdx.x * K1_CPB + warp;
  if (c >= NCH) return;

  const float4* p = reinterpret_cast<const float4*>(
      f0 + (size_t)b * Tn + c * CHUNK + lane * 8);
  float4 q0 = p[0], q1 = p[1];
  uint32_t acc = rad0_fx32(q0.x) + rad0_fx32(q0.y) + rad0_fx32(q0.z) + rad0_fx32(q0.w)
               + rad0_fx32(q1.x) + rad0_fx32(q1.y) + rad0_fx32(q1.z) + rad0_fx32(q1.w);
#pragma unroll
  for (int o = 16; o > 0; o >>= 1) acc += __shfl_down_sync(0xffffffffu, acc, o);
  if (lane == 0) g_pre0[b * NCH + c] = acc;
}

// ---------------- K2: exclusive scan of chunk sums (4 series) --------------
__global__ void k_scan() {
  int s = blockIdx.x;
  int lane = threadIdx.x;
  constexpr int PER = (NCH + 31) / 32;   // 59
  uint32_t* row = &g_pre0[(size_t)s * NCH];

  uint32_t v[PER];
  uint32_t tot = 0u;
  int st = lane * PER;
#pragma unroll
  for (int j = 0; j < PER; j++) {
    int c = st + j;
    v[j] = (c < NCH) ? row[c] : 0u;
    tot += v[j];
  }
  uint32_t x = tot;
#pragma unroll
  for (int o = 1; o < 32; o <<= 1) {
    uint32_t y = __shfl_up_sync(0xffffffffu, x, o);
    if (lane >= o) x += y;
  }
  uint32_t run = x - tot;
#pragma unroll
  for (int j = 0; j < PER; j++) {
    int c = st + j;
    if (c < NCH) {
      uint32_t old = v[j];
      row[c] = run;
      run += old;
    }
  }
}

// ---------------- K3: main — branch-free erfinv + per-lane rare fixup ------
__global__ void __launch_bounds__(TPB) k_main(const float* __restrict__ f0,
                                              float* __restrict__ out,
                                              RandIniFx ri, NKey nk) {
  int b = blockIdx.y, c = blockIdx.x;
  int base = c * CHUNK;
  int tid = threadIdx.x;
  int warp = tid >> 5, lane = tid & 31;
  int s0 = tid * SPT;

  __shared__ float so[CHUNK * DIMn];  // 9.2KB staging, sample-major
  __shared__ uint32_t wsum[TPB / 32];

  const float2 a = *reinterpret_cast<const float2*>(f0 + (size_t)b * Tn + base + s0);
  float fv0 = a.x, fv1 = a.y;

  uint32_t r00 = rad0_fx32(fv0), r01 = rad0_fx32(fv1);
  uint32_t a0 = r00 + r01;

  // warp scan (fundamental only)
  uint32_t x = a0;
#pragma unroll
  for (int o = 1; o < 32; o <<= 1) {
    uint32_t y = __shfl_up_sync(0xffffffffu, x, o);
    if (lane >= o) x += y;
  }
  if (lane == 31) wsum[warp] = x;
  uint32_t P = x - a0;
  __syncthreads();
#pragma unroll
  for (int w = 0; w < TPB / 32; w++)
    if (w < warp) P += wsum[w];
  P += g_pre0[b * NCH + c];

  uint32_t P1 = P + r00;               // inclusive fundamental @ sample j=0
  uint32_t P2 = P1 + r01;              // @ sample j=1

  // per-sample voiced mask (0.1 folded) / noise amplitude (sqrt2 folded)
  float uv0 = (fv0 > 0.0f) ? 1.0f : 0.0f;
  float uv1 = (fv1 > 0.0f) ? 1.0f : 0.0f;
  float am0 = (uv0 * 0.003f + (1.0f - uv0) * (0.1f / 3.0f)) * SQRT2F;
  float am1 = (uv1 * 0.003f + (1.0f - uv1) * (0.1f / 3.0f)) * SQRT2F;
  unsigned long long uvx, ampx;
  PK2(uvx, uv0 * 0.1f, uv1 * 0.1f);    // 0.1*uv: scales raw sin directly
  PK2(ampx, am0, am1);

  // packed constants
  unsigned long long c2m22, lo2, one2, mone2, mln2x, m2p5x;
  PK2(c2m22, 2.38418579101562500e-07f, 2.38418579101562500e-07f);  // 2^-22
  PK2(lo2,   LO_NORMAL, LO_NORMAL);
  PK2(one2,  1.0f, 1.0f);
  PK2(mone2,-1.0f,-1.0f);
  PK2(mln2x, -0.693147181f, -0.693147181f);
  PK2(m2p5x, -2.5f, -2.5f);
  unsigned long long e8,e7,e6,e5,e4,e3,e2,e1,e0;
  PK2(e8,  2.81022636e-08f,  2.81022636e-08f);
  PK2(e7,  3.43273939e-07f,  3.43273939e-07f);
  PK2(e6, -3.5233877e-06f,  -3.5233877e-06f);
  PK2(e5, -4.39150654e-06f, -4.39150654e-06f);
  PK2(e4,  0.00021858087f,   0.00021858087f);
  PK2(e3, -0.00125372503f,  -0.00125372503f);
  PK2(e2, -0.00417768164f,  -0.00417768164f);
  PK2(e1,  0.246640727f,     0.246640727f);
  PK2(e0,  1.50140941f,      1.50140941f);

  uint32_t riv[DIMn];
#pragma unroll
  for (int h = 0; h < DIMn; h++) riv[h] = ri.v[b * DIMn + h];

  uint32_t idxa = ((uint32_t)(b * Tn + base + s0)) * (uint32_t)DIMn;
  int slota = s0 * DIMn;
  const float C2PI = 1.46291807926715968e-09f;   // 2*pi/2^32

#pragma unroll
  for (int h = 0; h < DIMn; h++) {
    uint32_t pa = riv[h] + (uint32_t)(h + 1) * P1;
    uint32_t pb = riv[h] + (uint32_t)(h + 1) * P2;

    // ---- sine via MUFU: sin(phase * 2pi/2^32), scaled later by 0.1*uv ----
    float sa = __sinf((float)(int32_t)pa * C2PI);
    float sb = __sinf((float)(int32_t)pb * C2PI);
    unsigned long long sx;
    PK2(sx, sa, sb);

    // ---- noise: u = I2F(bits>>9)*2^-22 + LO  (bit-exact to reference) ----
    uint32_t ba = rng_bits(nk.k0, nk.k1, idxa + (uint32_t)h);
    uint32_t bb = rng_bits(nk.k0, nk.k1, idxa + 9u + (uint32_t)h);
    float ia = (float)(ba >> 9);       // I2F, exact (23-bit)
    float ib = (float)(bb >> 9);
    unsigned long long ix, ux, xx, vx;
    PK2(ix, ia, ib);
    FMA2(ux, ix, c2m22, lo2);          // u in [LO_NORMAL, 1-2^-24]
    MUL2(xx, ux, ux);
    FMA2(vx, xx, mone2, one2);         // v = 1 - u^2 > 0
    float va, vb;
    UPK2(va, vb, vx);
    float la = __log2f(va), lb = __log2f(vb);   // MUFU pipe
    unsigned long long lg;
    PK2(lg, la, lb);

    // branch-free packed fast path (valid for w < 5; fixed up below)
    unsigned long long ws, pq, nx;
    FMA2(ws, lg, mln2x, m2p5x);        // w - 2.5 in one op
    pq = e8;
    FMA2(pq, pq, ws, e7);
    FMA2(pq, pq, ws, e6);
    FMA2(pq, pq, ws, e5);
    FMA2(pq, pq, ws, e4);
    FMA2(pq, pq, ws, e3);
    FMA2(pq, pq, ws, e2);
    FMA2(pq, pq, ws, e1);
    FMA2(pq, pq, ws, e0);
    MUL2(nx, pq, ux);

    // rare per-lane tail fixup (P ~0.34%/lane): recompute only bad lanes
    if (va <= EXP_M5 || vb <= EXP_M5) {
      float na, nb, ua_, ub_;
      UPK2(na, nb, nx);
      UPK2(ua_, ub_, ux);
      if (va <= EXP_M5) na = erfinv_tail(ua_, la);
      if (vb <= EXP_M5) nb = erfinv_tail(ub_, lb);
      PK2(nx, na, nb);
    }

    unsigned long long swu, ox;
    MUL2(swu, sx, uvx);                // sin * (0.1*uv)
    FMA2(ox, ampx, nx, swu);           // ampx includes sqrt2
    float oa, ob;
    UPK2(oa, ob, ox);
    so[slota + h] = oa;
    so[slota + DIMn + h] = ob;
  }

  __syncthreads();
  // ---- writeout: 4x float4 + 1x float2, coalesced ----
  size_t outbase = ((size_t)b * Tn + (size_t)base) * (size_t)DIMn;
  {
    const float4* so4 = reinterpret_cast<const float4*>(so);
    float4* out4 = reinterpret_cast<float4*>(out + outbase);
#pragma unroll
    for (int i = 0; i < 4; i++)
      out4[i * TPB + tid] = so4[i * TPB + tid];
    const float2* so2 = reinterpret_cast<const float2*>(so + 2048);
    float2* out2 = reinterpret_cast<float2*>(out + outbase + 2048);
    out2[tid] = so2[tid];
  }
}

// ---------------- host ----------------
extern "C" void kernel_launch(void* const* d_in, const int* in_sizes, int n_in,
                              void* d_out, int out_size) {
  (void)in_sizes; (void)n_in; (void)out_size;
  const float* f0 = (const float*)d_in[0];
  float* out = (float*)d_out;

  uint32_t ik0, ik1, nk0, nk1;
  { uint32_t a, b;
    tf2x32(0u, 42u, 0u, 0u, a, b); ik0 = a; ik1 = b;
    tf2x32(0u, 42u, 0u, 1u, a, b); nk0 = a; nk1 = b; }

  RandIniFx ri;
  for (uint32_t i = 0; i < (uint32_t)(Bn * DIMn); i++) {
    uint32_t bits = rng_bits(ik0, ik1, i);
    float u = bits01(bits);
    if (u < 0.0f) u = 0.0f;
    ri.v[i] = (uint32_t)((double)u * 4294967296.0);  // u mult of 2^-23 -> exact
  }
  for (int b = 0; b < Bn; b++) ri.v[b * DIMn] = 0u;

  NKey nk{nk0, nk1};

  dim3 grid1(K1_GX, Bn);
  k_chunksum0<<<grid1, TPB>>>(f0);
  k_scan<<<Bn, 32>>>();
  dim3 grid3(NCH, Bn);
  k_main<<<grid3, TPB>>>(f0, out, ri, nk);
}